// round 12
// baseline (speedup 1.0000x reference)
#include <cuda_runtime.h>
#include <cuda_fp16.h>
#include <cstdint>

#define Bq    8
#define CIN   128
#define COUT  128
#define HH    256
#define WW    256
#define SDIM  512

#define PXW   20            // words per px in a plane (16 cp + 4 pad) -> conflict-free
#define NPX   66            // 64 px + 2 halo
#define KPL   (NPX * PXW)   // 1320 words per plane

__device__ float  g_style[Bq * CIN];
__device__ float  g_demod[Bq * COUT];
__device__ float  g_W2[COUT * CIN];
__device__ __half g_wU[48 * 4096];   // t=(g*4+k)*3+s, fragment-ordered U_k

#define MMA_F16(d, a, bb)                                                 \
    asm volatile("mma.sync.aligned.m16n8k16.row.col.f32.f16.f16.f32 "     \
                 "{%0,%1,%2,%3}, {%4,%5,%6,%7}, {%8,%9}, {%0,%1,%2,%3};"  \
                 : "+f"((d)[0]), "+f"((d)[1]), "+f"((d)[2]), "+f"((d)[3]) \
                 : "r"((a)[0]), "r"((a)[1]), "r"((a)[2]), "r"((a)[3]),    \
                   "r"((bb)[0]), "r"((bb)[1]))

// ---------------------------------------------------------------------------
// prep1: blocks 0..127 style GEMV (warp per (b,o)); blocks 128..191 W2
// ---------------------------------------------------------------------------
__global__ void prep1(const float* __restrict__ w,
                      const float* __restrict__ style_W,
                      const float* __restrict__ style_b,
                      const float* __restrict__ weight) {
    if (blockIdx.x < 128) {
        const int gw   = blockIdx.x * 8 + (threadIdx.x >> 5);
        const int lane = threadIdx.x & 31;
        const int b = gw >> 7, o = gw & 127;
        const float4* wv = (const float4*)(w + (size_t)b * SDIM);
        const float4* Wv = (const float4*)(style_W + (size_t)o * SDIM);
        float acc = 0.f;
        #pragma unroll
        for (int k = 0; k < 4; k++) {
            float4 a = wv[lane + k * 32], c = Wv[lane + k * 32];
            acc += a.x * c.x + a.y * c.y + a.z * c.z + a.w * c.w;
        }
        #pragma unroll
        for (int d = 16; d > 0; d >>= 1)
            acc += __shfl_xor_sync(0xffffffffu, acc, d);
        if (lane == 0) g_style[b * CIN + o] = acc + style_b[o];
    } else {
        int idx = (blockIdx.x - 128) * 256 + threadIdx.x;
        const float* p = weight + (size_t)idx * 9;
        float s = 0.f;
        #pragma unroll
        for (int t = 0; t < 9; t++) { float v = p[t]; s += v * v; }
        g_W2[idx] = s;
    }
}

// ---------------------------------------------------------------------------
// prep2: blocks 0..767 = U prepack (proven mapping; u3 = +w2 now); 768..895 demod
// ---------------------------------------------------------------------------
__global__ void prep2(const float* __restrict__ weight) {
    if (blockIdx.x < 768) {
        int idx  = blockIdx.x * 256 + threadIdx.x;     // < 196608
        int h    = idx & 1;
        int j    = (idx >> 1) & 3;
        int lane = (idx >> 3) & 31;
        int mt   = (idx >> 8) & 7;
        int kk   = (idx >> 11) & 1;
        int t    = idx >> 12;                          // 0..47
        int s  = t % 3;
        int q  = t / 3;
        int k  = q & 3;
        int g  = q >> 2;
        int m  = mt * 16 + (lane >> 2) + 8 * (j & 1);
        int kl = kk * 16 + (lane & 3) * 2 + 8 * (j >> 1) + h;
        int c  = g * 32 + kl;
        const float* wp = weight + ((size_t)m * CIN + c) * 9 + s;
        float w0 = wp[0], w1 = wp[3], w2 = wp[6];
        float u = (k == 0) ? w0
                : (k == 1) ? 0.5f * (w0 + w1 + w2)
                : (k == 2) ? 0.5f * (w0 - w1 + w2)
                : w2;
        g_wU[idx] = __float2half_rn(u);
    } else {
        int gw   = (blockIdx.x - 768) * 8 + (threadIdx.x >> 5);
        int lane = threadIdx.x & 31;
        int b = gw >> 7, o = gw & 127;
        float sum = 0.f;
        #pragma unroll
        for (int j = 0; j < 4; j++) {
            int i = lane + j * 32;
            float s = g_style[b * CIN + i];
            sum += s * s * g_W2[o * CIN + i];
        }
        #pragma unroll
        for (int d = 16; d > 0; d >>= 1)
            sum += __shfl_xor_sync(0xffffffffu, sum, d);
        if (lane == 0) g_demod[b * COUT + o] = rsqrtf(sum + 1e-8f);
    }
}

// ---------------------------------------------------------------------------
// main conv: CTA = (xq, ypair, b): 128 oc x 64 px x 2 rows, y-Winograd F(2,3).
// 8 warps = 2(wm: 64oc) x 4(wn: 16px). 4 plane accumulators held in regs for
// the whole loop; inverse transform ONCE in epilogue. 1 CTA/SM, 255 regs.
// ---------------------------------------------------------------------------
__global__ __launch_bounds__(256, 1)
void conv_mma_kernel(const float* __restrict__ x,
                     const float* __restrict__ bias,
                     float* __restrict__ out) {
    __shared__ float    styl[CIN];
    __shared__ uint32_t stage[2][4 * KPL];   // [buf][plane k][px][cp]

    const int tid  = threadIdx.x;
    const int lane = tid & 31;
    const int warp = tid >> 5;
    const int wm   = warp >> 2;      // 0..1
    const int wn   = warp & 3;       // 0..3
    const int x0   = blockIdx.x * 64;
    const int y0   = blockIdx.y * 2;
    const int b    = blockIdx.z;

    const int gid = lane >> 2;       // 0..7
    const int tig = lane & 3;        // 0..3

    if (tid < CIN) styl[tid] = g_style[b * CIN + tid];
    __syncthreads();

    // 4 Winograd-plane accumulators, 32 regs each
    float M0[4][2][4], M1[4][2][4], M2[4][2][4], M3[4][2][4];
    #pragma unroll
    for (int m = 0; m < 4; m++)
        #pragma unroll
        for (int n = 0; n < 2; n++)
            #pragma unroll
            for (int j = 0; j < 4; j++) {
                M0[m][n][j] = 0.f; M1[m][n][j] = 0.f;
                M2[m][n][j] = 0.f; M3[m][n][j] = 0.f;
            }

    // fill mapping
    const int fpx = tid >> 2;
    const int fc  = tid & 3;
    const int tpx = 64 + (lane >> 4);
    const int tcp = lane & 15;

    // ---- fill: 4 x-rows -> 4 transformed planes (style-scaled fp32 -> half2)
    auto fillg = [&](int g, uint32_t* buf) {
        const int c0 = g * 32;
        const bool ok0 = y0 > 0;
        const bool ok3 = y0 + 2 < HH;
        auto doItem = [&](int spx, int cp) {
            const int gx = x0 - 1 + spx;
            const bool xok = (unsigned)gx < (unsigned)WW;
            const int ch = c0 + 2 * cp;
            const float sA = styl[ch], sB = styl[ch + 1];
            const float* pA = x + (((size_t)b * CIN + ch) * HH + (y0 - 1)) * WW + gx;
            const float* pB = pA + (size_t)HH * WW;
            float dA[4] = {0.f, 0.f, 0.f, 0.f}, dB[4] = {0.f, 0.f, 0.f, 0.f};
            if (xok) {
                if (ok0) { dA[0] = __ldg(pA);          dB[0] = __ldg(pB); }
                dA[1] = __ldg(pA + WW);     dB[1] = __ldg(pB + WW);
                dA[2] = __ldg(pA + 2 * WW); dB[2] = __ldg(pB + 2 * WW);
                if (ok3) { dA[3] = __ldg(pA + 3 * WW); dB[3] = __ldg(pB + 3 * WW); }
            }
            #pragma unroll
            for (int r = 0; r < 4; r++) { dA[r] *= sA; dB[r] *= sB; }
            const uint32_t base = (uint32_t)(spx * PXW + cp);
            __half2 h0 = __floats2half2_rn(dA[0] - dA[2], dB[0] - dB[2]);
            __half2 h1 = __floats2half2_rn(dA[1] + dA[2], dB[1] + dB[2]);
            __half2 h2 = __floats2half2_rn(dA[2] - dA[1], dB[2] - dB[1]);
            __half2 h3 = __floats2half2_rn(dA[1] - dA[3], dB[1] - dB[3]);
            buf[0 * KPL + base] = *(uint32_t*)&h0;
            buf[1 * KPL + base] = *(uint32_t*)&h1;
            buf[2 * KPL + base] = *(uint32_t*)&h2;
            buf[3 * KPL + base] = *(uint32_t*)&h3;
        };
        #pragma unroll
        for (int ii = 0; ii < 4; ii++) doItem(fpx, fc + 4 * ii);
        if (warp == 0) doItem(tpx, tcp);
    };

    // ---- one plane (g,k) into acc: pure MMA + operand loads ----
    auto plane = [&](float (*acc)[2][4], const uint32_t* stg, int g, int k) {
        const uint32_t* pl = stg + k * KPL;
        #pragma unroll
        for (int s = 0; s < 3; s++) {
            const int t = (g * 4 + k) * 3 + s;
            #pragma unroll
            for (int kk = 0; kk < 2; kk++) {
                uint32_t bb[2][2];
                #pragma unroll
                for (int n = 0; n < 2; n++) {
                    const uint32_t* p = pl + (wn * 16 + n * 8 + gid + s) * PXW + kk * 8 + tig;
                    bb[n][0] = p[0];
                    bb[n][1] = p[4];
                }
                const uint4* As = ((const uint4*)g_wU) +
                                  (((size_t)(t * 2 + kk) * 8 + wm * 4) * 32 + lane);
                #pragma unroll
                for (int m = 0; m < 4; m++) {
                    uint4 a = __ldg(As + m * 32);
                    MMA_F16(acc[m][0], (const uint32_t*)&a, bb[0]);
                    MMA_F16(acc[m][1], (const uint32_t*)&a, bb[1]);
                }
            }
        }
    };

    fillg(0, stage[0]);
    __syncthreads();

    #pragma unroll 1
    for (int g = 0; g < 4; g++) {
        const int cur = g & 1;
        plane(M0, stage[cur], g, 0);
        if (g < 3) fillg(g + 1, stage[cur ^ 1]);   // LDG covered by planes 1-3
        plane(M1, stage[cur], g, 1);
        plane(M2, stage[cur], g, 2);
        plane(M3, stage[cur], g, 3);
        __syncthreads();
    }

    // ---- epilogue: inverse transform once + demod + bias, float2 stores ----
    #pragma unroll
    for (int m = 0; m < 4; m++) {
        const int oc0 = wm * 64 + m * 16 + gid;
        const int oc1 = oc0 + 8;
        const float dm0 = g_demod[b * COUT + oc0], bs0 = bias[oc0];
        const float dm1 = g_demod[b * COUT + oc1], bs1 = bias[oc1];
        float* p00 = out + (((size_t)b * COUT + oc0) * HH + y0) * WW;
        float* p01 = p00 + WW;
        float* p10 = out + (((size_t)b * COUT + oc1) * HH + y0) * WW;
        float* p11 = p10 + WW;
        #pragma unroll
        for (int n = 0; n < 2; n++) {
            const int px = x0 + wn * 16 + n * 8 + tig * 2;
            float y0v[4], y1v[4];
            #pragma unroll
            for (int j = 0; j < 4; j++) {
                y0v[j] = M0[m][n][j] + M1[m][n][j] + M2[m][n][j];
                y1v[j] = M1[m][n][j] - M2[m][n][j] - M3[m][n][j];
            }
            *(float2*)(p00 + px) = make_float2(y0v[0] * dm0 + bs0, y0v[1] * dm0 + bs0);
            *(float2*)(p01 + px) = make_float2(y1v[0] * dm0 + bs0, y1v[1] * dm0 + bs0);
            *(float2*)(p10 + px) = make_float2(y0v[2] * dm1 + bs1, y0v[3] * dm1 + bs1);
            *(float2*)(p11 + px) = make_float2(y1v[2] * dm1 + bs1, y1v[3] * dm1 + bs1);
        }
    }
}

// ---------------------------------------------------------------------------
extern "C" void kernel_launch(void* const* d_in, const int* in_sizes, int n_in,
                              void* d_out, int out_size) {
    const float* x       = (const float*)d_in[0];
    const float* w       = (const float*)d_in[1];
    const float* weight  = (const float*)d_in[2];
    const float* style_W = (const float*)d_in[3];
    const float* style_b = (const float*)d_in[4];
    const float* bias    = (const float*)d_in[5];
    float* out = (float*)d_out;

    prep1<<<192, 256>>>(w, style_W, style_b, weight);
    prep2<<<896, 256>>>(weight);

    dim3 grid(4, HH / 2, Bq);
    conv_mma_kernel<<<grid, 256>>>(x, bias, out);
}

// round 13
// speedup vs baseline: 1.4695x; 1.4695x over previous
#include <cuda_runtime.h>
#include <cuda_fp16.h>
#include <cstdint>

#define Bq    8
#define CIN   128
#define COUT  128
#define HH    256
#define WW    256
#define SDIM  512

#define PXW   36     // words (half2) per px row: 32 used + 4 pad; 4*gid+tig mod 32 -> conflict-free
#define NPX   130    // 128 px + 2 halo

__device__ float  g_style[Bq * CIN];
__device__ float  g_demod[Bq * COUT];
__device__ float  g_W2[COUT * CIN];
__device__ __half g_wA[36 * 8192];   // fragment-ordered fp16 weights (R6-R8 proven layout)

#define MMA_F16(d, a, bb)                                                 \
    asm volatile("mma.sync.aligned.m16n8k16.row.col.f32.f16.f16.f32 "     \
                 "{%0,%1,%2,%3}, {%4,%5,%6,%7}, {%8,%9}, {%0,%1,%2,%3};"  \
                 : "+f"((d)[0]), "+f"((d)[1]), "+f"((d)[2]), "+f"((d)[3]) \
                 : "r"((a)[0]), "r"((a)[1]), "r"((a)[2]), "r"((a)[3]),    \
                   "r"((bb)[0]), "r"((bb)[1]))

// ---------------------------------------------------------------------------
// prep1: blocks 0..127 style GEMV; 128..191 W2; 192..1343 weight prepack.
// All three phases are mutually independent -> one launch.
// ---------------------------------------------------------------------------
__global__ void prep1(const float* __restrict__ w,
                      const float* __restrict__ style_W,
                      const float* __restrict__ style_b,
                      const float* __restrict__ weight) {
    if (blockIdx.x < 128) {
        const int gw   = blockIdx.x * 8 + (threadIdx.x >> 5);  // 0..1023
        const int lane = threadIdx.x & 31;
        const int b = gw >> 7, o = gw & 127;
        const float4* wv = (const float4*)(w + (size_t)b * SDIM);
        const float4* Wv = (const float4*)(style_W + (size_t)o * SDIM);
        float acc = 0.f;
        #pragma unroll
        for (int k = 0; k < 4; k++) {
            float4 a = wv[lane + k * 32], c = Wv[lane + k * 32];
            acc += a.x * c.x + a.y * c.y + a.z * c.z + a.w * c.w;
        }
        #pragma unroll
        for (int d = 16; d > 0; d >>= 1)
            acc += __shfl_xor_sync(0xffffffffu, acc, d);
        if (lane == 0) g_style[b * CIN + o] = acc + style_b[o];
    } else if (blockIdx.x < 192) {
        int idx = (blockIdx.x - 128) * 256 + threadIdx.x;   // < 16384
        const float* p = weight + (size_t)idx * 9;
        float s = 0.f;
        #pragma unroll
        for (int t = 0; t < 9; t++) { float v = p[t]; s += v * v; }
        g_W2[idx] = s;
    } else {
        // prepack into m16n8k16 fp16 A-fragment order (proven R6-R8 mapping)
        int idx = (blockIdx.x - 192) * 256 + threadIdx.x;   // < 294912
        int h    = idx & 1;
        int j    = (idx >> 1) & 3;
        int lane = (idx >> 3) & 31;
        int mt   = (idx >> 8) & 7;
        int kk   = (idx >> 11) & 1;
        int s    = idx >> 12;                               // 0..35
        int dx = s % 3;
        int g  = s / 3;
        int dy = g >> 2, chunk = g & 3;
        int m  = mt * 16 + (lane >> 2) + 8 * (j & 1);
        int kl = kk * 16 + (lane & 3) * 2 + 8 * (j >> 1) + h;
        int c  = chunk * 32 + kl;
        g_wA[idx] = __float2half_rn(weight[((size_t)m * CIN + c) * 9 + dy * 3 + dx]);
    }
}

// ---------------------------------------------------------------------------
// prep2: demod only (needs style + W2)
// ---------------------------------------------------------------------------
__global__ void prep2(void) {
    int gw   = blockIdx.x * 8 + (threadIdx.x >> 5);   // 0..1023
    int lane = threadIdx.x & 31;
    int b = gw >> 7, o = gw & 127;
    float sum = 0.f;
    #pragma unroll
    for (int j = 0; j < 4; j++) {
        int i = lane + j * 32;
        float s = g_style[b * CIN + i];
        sum += s * s * g_W2[o * CIN + i];
    }
    #pragma unroll
    for (int d = 16; d > 0; d >>= 1)
        sum += __shfl_xor_sync(0xffffffffu, sum, d);
    if (lane == 0) g_demod[b * COUT + o] = rsqrtf(sum + 1e-8f);
}

// ---------------------------------------------------------------------------
// main conv: CTA = (xhalf, y, b). M=128 x N=128 x K=1152, fp16 m16n8k16.
// 8 warps = 2(wm: 64oc) x 4(wn: 32px). 6 groups of (dy, 64-channel chunk).
// Stage: fp16 half2 transposed [px][cp0..31], PXW=36 -> conflict-free.
// ---------------------------------------------------------------------------
__global__ __launch_bounds__(256, 2)
void conv_mma_kernel(const float* __restrict__ x,
                     const float* __restrict__ bias,
                     float* __restrict__ out) {
    __shared__ float    styl[CIN];
    __shared__ uint32_t stage[2][NPX * PXW];

    const int tid  = threadIdx.x;
    const int lane = tid & 31;
    const int warp = tid >> 5;
    const int wm   = warp >> 2;      // 0..1
    const int wn   = warp & 3;       // 0..3
    const int xh   = blockIdx.x;
    const int y    = blockIdx.y;
    const int b    = blockIdx.z;
    const int x0   = xh * 128;

    const int gid = lane >> 2;       // 0..7
    const int tig = lane & 3;        // 0..3

    if (tid < CIN) styl[tid] = g_style[b * CIN + tid];
    __syncthreads();

    float acc[4][4][4];
    #pragma unroll
    for (int m = 0; m < 4; m++)
        #pragma unroll
        for (int n = 0; n < 4; n++)
            #pragma unroll
            for (int j = 0; j < 4; j++) acc[m][n][j] = 0.f;

    // fill mapping: px = jj*64 + (tid>>2), cp = (tid&3) + 4*ii (ii 0..7)
    const int fpx = tid >> 2;        // 0..63
    const int fc  = tid & 3;
    // tail px 128,129 x cp 0..31: warp0 cp 0..15, warp1 cp 16..31
    const int tpx = 128 + (lane >> 4);
    const int tcp = (warp & 1) * 16 + (lane & 15);

    // ---- fill one stage buffer for group G=(dy,chunk64): 64 ch x 130 px ----
    auto fill = [&](int G, uint32_t* buf) {
        const int dy = G >> 1, c0 = (G & 1) * 64;
        const int yr = y + dy - 1;
        const bool yok = (unsigned)yr < (unsigned)HH;
        const float* xp = x + (((size_t)b * CIN + c0) * HH + yr) * WW;
        #pragma unroll
        for (int jj = 0; jj < 2; jj++) {
            const int px = jj * 64 + fpx;
            const int gx = x0 - 1 + px;
            const bool ok = yok && ((unsigned)gx < (unsigned)WW);
            #pragma unroll
            for (int ii = 0; ii < 8; ii++) {
                const int cp = fc + ii * 4;
                float v0 = 0.f, v1 = 0.f;
                if (ok) {
                    v0 = __ldg(xp + (size_t)(2 * cp)     * HH * WW + gx) * styl[c0 + 2 * cp];
                    v1 = __ldg(xp + (size_t)(2 * cp + 1) * HH * WW + gx) * styl[c0 + 2 * cp + 1];
                }
                __half2 hv = __floats2half2_rn(v0, v1);
                buf[px * PXW + cp] = *(uint32_t*)&hv;
            }
        }
        if (warp < 2) {
            const int gx = x0 - 1 + tpx;
            float v0 = 0.f, v1 = 0.f;
            if (yok && gx < WW) {
                v0 = __ldg(xp + (size_t)(2 * tcp)     * HH * WW + gx) * styl[c0 + 2 * tcp];
                v1 = __ldg(xp + (size_t)(2 * tcp + 1) * HH * WW + gx) * styl[c0 + 2 * tcp + 1];
            }
            __half2 hv = __floats2half2_rn(v0, v1);
            buf[tpx * PXW + tcp] = *(uint32_t*)&hv;
        }
    };

    // ---- one dx-step of group G: 4 kk x (4 A-LDG.128, 8 B-LDS, 16 MMA) ----
    auto compute = [&](const uint32_t* stg, int G, int dx) {
        const int dy = G >> 1, C = G & 1;
        #pragma unroll
        for (int kk = 0; kk < 4; kk++) {
            const int s = (dy * 4 + C * 2 + (kk >> 1)) * 3 + dx;   // 0..35
            const uint4* As = ((const uint4*)g_wA) +
                              (((size_t)(s * 2 + (kk & 1)) * 8 + wm * 4) * 32 + lane);
            uint4 af[4];
            #pragma unroll
            for (int m = 0; m < 4; m++) af[m] = __ldg(As + m * 32);

            uint32_t bb[4][2];
            #pragma unroll
            for (int n = 0; n < 4; n++) {
                const int px = wn * 32 + n * 8 + gid + dx;
                const uint32_t* p = stg + px * PXW + kk * 8 + tig;
                bb[n][0] = p[0];
                bb[n][1] = p[4];
            }
            #pragma unroll
            for (int m = 0; m < 4; m++) {
                const uint32_t* a = (const uint32_t*)&af[m];
                #pragma unroll
                for (int n = 0; n < 4; n++)
                    MMA_F16(acc[m][n], a, bb[n]);
            }
        }
    };

    fill(0, stage[0]);
    __syncthreads();

    #pragma unroll 1
    for (int G = 0; G < 6; G++) {
        const int cur = G & 1;
        compute(stage[cur], G, 0);
        if (G < 5) fill(G + 1, stage[cur ^ 1]);   // LDG in flight across dx=1,2
        compute(stage[cur], G, 1);
        compute(stage[cur], G, 2);
        __syncthreads();
    }

    // ---- epilogue: demod + bias, float2 stores (verbatim R7) ----
    #pragma unroll
    for (int m = 0; m < 4; m++) {
        const int oc0 = (wm * 4 + m) * 16 + gid;
        const int oc1 = oc0 + 8;
        const float d0 = g_demod[b * COUT + oc0], bb0 = bias[oc0];
        const float d1 = g_demod[b * COUT + oc1], bb1 = bias[oc1];
        float* r0 = out + (((size_t)b * COUT + oc0) * HH + y) * WW;
        float* r1 = out + (((size_t)b * COUT + oc1) * HH + y) * WW;
        #pragma unroll
        for (int n = 0; n < 4; n++) {
            const int px = x0 + (wn * 4 + n) * 8 + tig * 2;
            float2 v0 = make_float2(acc[m][n][0] * d0 + bb0, acc[m][n][1] * d0 + bb0);
            float2 v1 = make_float2(acc[m][n][2] * d1 + bb1, acc[m][n][3] * d1 + bb1);
            *(float2*)(r0 + px) = v0;
            *(float2*)(r1 + px) = v1;
        }
    }
}

// ---------------------------------------------------------------------------
extern "C" void kernel_launch(void* const* d_in, const int* in_sizes, int n_in,
                              void* d_out, int out_size) {
    const float* x       = (const float*)d_in[0];
    const float* w       = (const float*)d_in[1];
    const float* weight  = (const float*)d_in[2];
    const float* style_W = (const float*)d_in[3];
    const float* style_b = (const float*)d_in[4];
    const float* bias    = (const float*)d_in[5];
    float* out = (float*)d_out;

    prep1<<<1344, 256>>>(w, style_W, style_b, weight);
    prep2<<<128, 256>>>();

    dim3 grid(2, HH, Bq);
    conv_mma_kernel<<<grid, 256>>>(x, bias, out);
}

// round 14
// speedup vs baseline: 1.5246x; 1.0375x over previous
#include <cuda_runtime.h>
#include <cuda_fp16.h>
#include <cstdint>

#define Bq    8
#define CIN   128
#define COUT  128
#define HH    256
#define WW    256
#define SDIM  512

#define PXW   68     // words (half2) per px row: 64 used + 4 pad; 4*gid+tig mod 32 -> conflict-free
#define NPX   130    // 128 px + 2 halo

__device__ float  g_style[Bq * CIN];
__device__ float  g_demod[Bq * COUT];
__device__ float  g_W2[COUT * CIN];
__device__ __half g_wA[36 * 8192];   // fragment-ordered fp16 weights (R6-R13 proven layout)

#define MMA_F16(d, a, bb)                                                 \
    asm volatile("mma.sync.aligned.m16n8k16.row.col.f32.f16.f16.f32 "     \
                 "{%0,%1,%2,%3}, {%4,%5,%6,%7}, {%8,%9}, {%0,%1,%2,%3};"  \
                 : "+f"((d)[0]), "+f"((d)[1]), "+f"((d)[2]), "+f"((d)[3]) \
                 : "r"((a)[0]), "r"((a)[1]), "r"((a)[2]), "r"((a)[3]),    \
                   "r"((bb)[0]), "r"((bb)[1]))

// ---------------------------------------------------------------------------
// prep1: blocks 0..127 style GEMV; 128..191 W2; 192..1343 weight prepack.
// ---------------------------------------------------------------------------
__global__ void prep1(const float* __restrict__ w,
                      const float* __restrict__ style_W,
                      const float* __restrict__ style_b,
                      const float* __restrict__ weight) {
    if (blockIdx.x < 128) {
        const int gw   = blockIdx.x * 8 + (threadIdx.x >> 5);
        const int lane = threadIdx.x & 31;
        const int b = gw >> 7, o = gw & 127;
        const float4* wv = (const float4*)(w + (size_t)b * SDIM);
        const float4* Wv = (const float4*)(style_W + (size_t)o * SDIM);
        float acc = 0.f;
        #pragma unroll
        for (int k = 0; k < 4; k++) {
            float4 a = wv[lane + k * 32], c = Wv[lane + k * 32];
            acc += a.x * c.x + a.y * c.y + a.z * c.z + a.w * c.w;
        }
        #pragma unroll
        for (int d = 16; d > 0; d >>= 1)
            acc += __shfl_xor_sync(0xffffffffu, acc, d);
        if (lane == 0) g_style[b * CIN + o] = acc + style_b[o];
    } else if (blockIdx.x < 192) {
        int idx = (blockIdx.x - 128) * 256 + threadIdx.x;
        const float* p = weight + (size_t)idx * 9;
        float s = 0.f;
        #pragma unroll
        for (int t = 0; t < 9; t++) { float v = p[t]; s += v * v; }
        g_W2[idx] = s;
    } else {
        int idx = (blockIdx.x - 192) * 256 + threadIdx.x;   // < 294912
        int h    = idx & 1;
        int j    = (idx >> 1) & 3;
        int lane = (idx >> 3) & 31;
        int mt   = (idx >> 8) & 7;
        int kk   = (idx >> 11) & 1;
        int s    = idx >> 12;                               // 0..35
        int dx = s % 3;
        int g  = s / 3;
        int dy = g >> 2, chunk = g & 3;
        int m  = mt * 16 + (lane >> 2) + 8 * (j & 1);
        int kl = kk * 16 + (lane & 3) * 2 + 8 * (j >> 1) + h;
        int c  = chunk * 32 + kl;
        g_wA[idx] = __float2half_rn(weight[((size_t)m * CIN + c) * 9 + dy * 3 + dx]);
    }
}

// ---------------------------------------------------------------------------
// prep2: demod only
// ---------------------------------------------------------------------------
__global__ void prep2(void) {
    int gw   = blockIdx.x * 8 + (threadIdx.x >> 5);
    int lane = threadIdx.x & 31;
    int b = gw >> 7, o = gw & 127;
    float sum = 0.f;
    #pragma unroll
    for (int j = 0; j < 4; j++) {
        int i = lane + j * 32;
        float s = g_style[b * CIN + i];
        sum += s * s * g_W2[o * CIN + i];
    }
    #pragma unroll
    for (int d = 16; d > 0; d >>= 1)
        sum += __shfl_xor_sync(0xffffffffu, sum, d);
    if (lane == 0) g_demod[b * COUT + o] = rsqrtf(sum + 1e-8f);
}

// ---------------------------------------------------------------------------
// main conv: CTA = (xhalf, y, b). M=128 x N=128 x K=1152, fp16 m16n8k16.
// 8 warps = 2(wm: 64oc) x 4(wn: 32px). 3 groups = dy, each FULL 128 channels.
// Stage: fp16 half2 transposed [px][cp0..63], PXW=68 -> conflict-free.
// ---------------------------------------------------------------------------
__global__ __launch_bounds__(256, 2)
void conv_mma_kernel(const float* __restrict__ x,
                     const float* __restrict__ bias,
                     float* __restrict__ out) {
    __shared__ float    styl[CIN];
    __shared__ uint32_t stage[2][NPX * PXW];

    const int tid  = threadIdx.x;
    const int lane = tid & 31;
    const int warp = tid >> 5;
    const int wm   = warp >> 2;      // 0..1
    const int wn   = warp & 3;       // 0..3
    const int xh   = blockIdx.x;
    const int y    = blockIdx.y;
    const int b    = blockIdx.z;
    const int x0   = xh * 128;

    const int gid = lane >> 2;       // 0..7
    const int tig = lane & 3;        // 0..3

    if (tid < CIN) styl[tid] = g_style[b * CIN + tid];
    __syncthreads();

    float acc[4][4][4];
    #pragma unroll
    for (int m = 0; m < 4; m++)
        #pragma unroll
        for (int n = 0; n < 4; n++)
            #pragma unroll
            for (int j = 0; j < 4; j++) acc[m][n][j] = 0.f;

    // fill mapping: px = jj*64 + (tid>>2), cp = (tid&3) + 4*ii (ii 0..15)
    const int fpx = tid >> 2;        // 0..63
    const int fc  = tid & 3;
    // tail px 128,129 x cp 0..63: warps 0..3, each 32 cp of one px
    const int tpx = 128 + (warp >> 1);
    const int tcp = (warp & 1) * 32 + lane;

    // ---- fill one stage buffer for group dy: 128 ch x 130 px ----
    auto fill = [&](int dy, uint32_t* buf) {
        const int yr = y + dy - 1;
        const bool yok = (unsigned)yr < (unsigned)HH;
        const float* xp = x + (((size_t)b * CIN) * HH + yr) * WW;
        #pragma unroll
        for (int jj = 0; jj < 2; jj++) {
            const int px = jj * 64 + fpx;
            const int gx = x0 - 1 + px;
            const bool ok = yok && ((unsigned)gx < (unsigned)WW);
            #pragma unroll
            for (int ii = 0; ii < 16; ii++) {
                const int cp = fc + ii * 4;
                float v0 = 0.f, v1 = 0.f;
                if (ok) {
                    v0 = __ldg(xp + (size_t)(2 * cp)     * HH * WW + gx) * styl[2 * cp];
                    v1 = __ldg(xp + (size_t)(2 * cp + 1) * HH * WW + gx) * styl[2 * cp + 1];
                }
                __half2 hv = __floats2half2_rn(v0, v1);
                buf[px * PXW + cp] = *(uint32_t*)&hv;
            }
        }
        if (warp < 4) {
            const int gx = x0 - 1 + tpx;
            float v0 = 0.f, v1 = 0.f;
            if (yok && gx < WW) {
                v0 = __ldg(xp + (size_t)(2 * tcp)     * HH * WW + gx) * styl[2 * tcp];
                v1 = __ldg(xp + (size_t)(2 * tcp + 1) * HH * WW + gx) * styl[2 * tcp + 1];
            }
            __half2 hv = __floats2half2_rn(v0, v1);
            buf[tpx * PXW + tcp] = *(uint32_t*)&hv;
        }
    };

    // ---- one dx-step of group dy: 8 kk x (4 A-LDG.128, 8 B-LDS, 16 MMA) ----
    auto compute = [&](const uint32_t* stg, int dy, int dx) {
        #pragma unroll
        for (int kk = 0; kk < 8; kk++) {
            const int s = (dy * 4 + (kk >> 1)) * 3 + dx;   // 0..35 (proven g_wA layout)
            const uint4* As = ((const uint4*)g_wA) +
                              (((size_t)(s * 2 + (kk & 1)) * 8 + wm * 4) * 32 + lane);
            uint4 af[4];
            #pragma unroll
            for (int m = 0; m < 4; m++) af[m] = __ldg(As + m * 32);

            uint32_t bb[4][2];
            #pragma unroll
            for (int n = 0; n < 4; n++) {
                const int px = wn * 32 + n * 8 + gid + dx;
                const uint32_t* p = stg + px * PXW + kk * 8 + tig;
                bb[n][0] = p[0];
                bb[n][1] = p[4];
            }
            #pragma unroll
            for (int m = 0; m < 4; m++) {
                const uint32_t* a = (const uint32_t*)&af[m];
                #pragma unroll
                for (int n = 0; n < 4; n++)
                    MMA_F16(acc[m][n], a, bb[n]);
            }
        }
    };

    fill(0, stage[0]);
    __syncthreads();

    #pragma unroll 1
    for (int G = 0; G < 3; G++) {
        const int cur = G & 1;
        compute(stage[cur], G, 0);
        if (G < 2) fill(G + 1, stage[cur ^ 1]);   // LDG in flight across dx=1,2
        compute(stage[cur], G, 1);
        compute(stage[cur], G, 2);
        __syncthreads();
    }

    // ---- epilogue: demod + bias, float2 stores ----
    #pragma unroll
    for (int m = 0; m < 4; m++) {
        const int oc0 = (wm * 4 + m) * 16 + gid;
        const int oc1 = oc0 + 8;
        const float d0 = g_demod[b * COUT + oc0], bb0 = bias[oc0];
        const float d1 = g_demod[b * COUT + oc1], bb1 = bias[oc1];
        float* r0 = out + (((size_t)b * COUT + oc0) * HH + y) * WW;
        float* r1 = out + (((size_t)b * COUT + oc1) * HH + y) * WW;
        #pragma unroll
        for (int n = 0; n < 4; n++) {
            const int px = x0 + (wn * 4 + n) * 8 + tig * 2;
            float2 v0 = make_float2(acc[m][n][0] * d0 + bb0, acc[m][n][1] * d0 + bb0);
            float2 v1 = make_float2(acc[m][n][2] * d1 + bb1, acc[m][n][3] * d1 + bb1);
            *(float2*)(r0 + px) = v0;
            *(float2*)(r1 + px) = v1;
        }
    }
}

// ---------------------------------------------------------------------------
extern "C" void kernel_launch(void* const* d_in, const int* in_sizes, int n_in,
                              void* d_out, int out_size) {
    const float* x       = (const float*)d_in[0];
    const float* w       = (const float*)d_in[1];
    const float* weight  = (const float*)d_in[2];
    const float* style_W = (const float*)d_in[3];
    const float* style_b = (const float*)d_in[4];
    const float* bias    = (const float*)d_in[5];
    float* out = (float*)d_out;

    prep1<<<1344, 256>>>(w, style_W, style_b, weight);
    prep2<<<128, 256>>>();

    dim3 grid(2, HH, Bq);
    conv_mma_kernel<<<grid, 256>>>(x, bias, out);
}

// round 15
// speedup vs baseline: 1.5522x; 1.0181x over previous
#include <cuda_runtime.h>
#include <cuda_fp16.h>
#include <cstdint>

#define Bq    8
#define CIN   128
#define COUT  128
#define HH    256
#define WW    256
#define SDIM  512

#define PXW   68     // words (half2) per px row: 64 used + 4 pad; 4*gid+tig mod 32 -> conflict-free
#define NPX   130    // 128 px + 2 halo

__device__ float  g_style[Bq * CIN];
__device__ float  g_demod[Bq * COUT];
__device__ float  g_W2[COUT * CIN];
__device__ __half g_wA[36 * 8192];   // fragment-ordered fp16 weights (R6-R14 proven layout)

#define MMA_F16(d, a, bb)                                                 \
    asm volatile("mma.sync.aligned.m16n8k16.row.col.f32.f16.f16.f32 "     \
                 "{%0,%1,%2,%3}, {%4,%5,%6,%7}, {%8,%9}, {%0,%1,%2,%3};"  \
                 : "+f"((d)[0]), "+f"((d)[1]), "+f"((d)[2]), "+f"((d)[3]) \
                 : "r"((a)[0]), "r"((a)[1]), "r"((a)[2]), "r"((a)[3]),    \
                   "r"((bb)[0]), "r"((bb)[1]))

// ---------------------------------------------------------------------------
// prep1: blocks 0..127 style GEMV; 128..191 W2; 192..1343 weight prepack.
// ---------------------------------------------------------------------------
__global__ void prep1(const float* __restrict__ w,
                      const float* __restrict__ style_W,
                      const float* __restrict__ style_b,
                      const float* __restrict__ weight) {
    if (blockIdx.x < 128) {
        const int gw   = blockIdx.x * 8 + (threadIdx.x >> 5);
        const int lane = threadIdx.x & 31;
        const int b = gw >> 7, o = gw & 127;
        const float4* wv = (const float4*)(w + (size_t)b * SDIM);
        const float4* Wv = (const float4*)(style_W + (size_t)o * SDIM);
        float acc = 0.f;
        #pragma unroll
        for (int k = 0; k < 4; k++) {
            float4 a = wv[lane + k * 32], c = Wv[lane + k * 32];
            acc += a.x * c.x + a.y * c.y + a.z * c.z + a.w * c.w;
        }
        #pragma unroll
        for (int d = 16; d > 0; d >>= 1)
            acc += __shfl_xor_sync(0xffffffffu, acc, d);
        if (lane == 0) g_style[b * CIN + o] = acc + style_b[o];
    } else if (blockIdx.x < 192) {
        int idx = (blockIdx.x - 128) * 256 + threadIdx.x;
        const float* p = weight + (size_t)idx * 9;
        float s = 0.f;
        #pragma unroll
        for (int t = 0; t < 9; t++) { float v = p[t]; s += v * v; }
        g_W2[idx] = s;
    } else {
        int idx = (blockIdx.x - 192) * 256 + threadIdx.x;   // < 294912
        int h    = idx & 1;
        int j    = (idx >> 1) & 3;
        int lane = (idx >> 3) & 31;
        int mt   = (idx >> 8) & 7;
        int kk   = (idx >> 11) & 1;
        int s    = idx >> 12;                               // 0..35
        int dx = s % 3;
        int g  = s / 3;
        int dy = g >> 2, chunk = g & 3;
        int m  = mt * 16 + (lane >> 2) + 8 * (j & 1);
        int kl = kk * 16 + (lane & 3) * 2 + 8 * (j >> 1) + h;
        int c  = chunk * 32 + kl;
        g_wA[idx] = __float2half_rn(weight[((size_t)m * CIN + c) * 9 + dy * 3 + dx]);
    }
}

// ---------------------------------------------------------------------------
// prep2: demod only
// ---------------------------------------------------------------------------
__global__ void prep2(void) {
    int gw   = blockIdx.x * 8 + (threadIdx.x >> 5);
    int lane = threadIdx.x & 31;
    int b = gw >> 7, o = gw & 127;
    float sum = 0.f;
    #pragma unroll
    for (int j = 0; j < 4; j++) {
        int i = lane + j * 32;
        float s = g_style[b * CIN + i];
        sum += s * s * g_W2[o * CIN + i];
    }
    #pragma unroll
    for (int d = 16; d > 0; d >>= 1)
        sum += __shfl_xor_sync(0xffffffffu, sum, d);
    if (lane == 0) g_demod[b * COUT + o] = rsqrtf(sum + 1e-8f);
}

// ---------------------------------------------------------------------------
// main conv: CTA = (xhalf, y, b). M=128 x N=128 x K=1152, fp16 m16n8k16.
// 8 warps = 2(wm: 64oc) x 4(wn: 32px). 3 dy-groups of full 128 channels.
// A-fragments software-pipelined one kk ahead (hide L1/L2 latency).
// ---------------------------------------------------------------------------
__global__ __launch_bounds__(256, 2)
void conv_mma_kernel(const float* __restrict__ x,
                     const float* __restrict__ bias,
                     float* __restrict__ out) {
    __shared__ float    styl[CIN];
    __shared__ uint32_t stage[2][NPX * PXW];

    const int tid  = threadIdx.x;
    const int lane = tid & 31;
    const int warp = tid >> 5;
    const int wm   = warp >> 2;      // 0..1
    const int wn   = warp & 3;       // 0..3
    const int xh   = blockIdx.x;
    const int y    = blockIdx.y;
    const int b    = blockIdx.z;
    const int x0   = xh * 128;

    const int gid = lane >> 2;       // 0..7
    const int tig = lane & 3;        // 0..3

    if (tid < CIN) styl[tid] = g_style[b * CIN + tid];
    __syncthreads();

    float acc[4][4][4];
    #pragma unroll
    for (int m = 0; m < 4; m++)
        #pragma unroll
        for (int n = 0; n < 4; n++)
            #pragma unroll
            for (int j = 0; j < 4; j++) acc[m][n][j] = 0.f;

    // fill mapping: px = jj*64 + (tid>>2), cp = (tid&3) + 4*ii (ii 0..15)
    const int fpx = tid >> 2;
    const int fc  = tid & 3;
    const int tpx = 128 + (warp >> 1);
    const int tcp = (warp & 1) * 32 + lane;

    // ---- fill one stage buffer for group dy: 128 ch x 130 px ----
    auto fill = [&](int dy, uint32_t* buf) {
        const int yr = y + dy - 1;
        const bool yok = (unsigned)yr < (unsigned)HH;
        const float* xp = x + (((size_t)b * CIN) * HH + yr) * WW;
        #pragma unroll
        for (int jj = 0; jj < 2; jj++) {
            const int px = jj * 64 + fpx;
            const int gx = x0 - 1 + px;
            const bool ok = yok && ((unsigned)gx < (unsigned)WW);
            #pragma unroll
            for (int ii = 0; ii < 16; ii++) {
                const int cp = fc + ii * 4;
                float v0 = 0.f, v1 = 0.f;
                if (ok) {
                    v0 = __ldg(xp + (size_t)(2 * cp)     * HH * WW + gx) * styl[2 * cp];
                    v1 = __ldg(xp + (size_t)(2 * cp + 1) * HH * WW + gx) * styl[2 * cp + 1];
                }
                __half2 hv = __floats2half2_rn(v0, v1);
                buf[px * PXW + cp] = *(uint32_t*)&hv;
            }
        }
        if (warp < 4) {
            const int gx = x0 - 1 + tpx;
            float v0 = 0.f, v1 = 0.f;
            if (yok && gx < WW) {
                v0 = __ldg(xp + (size_t)(2 * tcp)     * HH * WW + gx) * styl[2 * tcp];
                v1 = __ldg(xp + (size_t)(2 * tcp + 1) * HH * WW + gx) * styl[2 * tcp + 1];
            }
            __half2 hv = __floats2half2_rn(v0, v1);
            buf[tpx * PXW + tcp] = *(uint32_t*)&hv;
        }
    };

    // A-fragment pointer for (kk, dy, dx)
    auto Aptr = [&](int dy, int dx, int kk) -> const uint4* {
        const int s = (dy * 4 + (kk >> 1)) * 3 + dx;
        return ((const uint4*)g_wA) +
               (((size_t)(s * 2 + (kk & 1)) * 8 + wm * 4) * 32 + lane);
    };

    // ---- one dx-step: A-fragments prefetched one kk ahead ----
    auto compute = [&](const uint32_t* stg, int dy, int dx) {
        uint4 af[4];
        {
            const uint4* As = Aptr(dy, dx, 0);
            #pragma unroll
            for (int m = 0; m < 4; m++) af[m] = __ldg(As + m * 32);
        }
        #pragma unroll
        for (int kk = 0; kk < 8; kk++) {
            // prefetch next kk's A-fragments before issuing this kk's MMAs
            uint4 afn[4];
            if (kk < 7) {
                const uint4* As = Aptr(dy, dx, kk + 1);
                #pragma unroll
                for (int m = 0; m < 4; m++) afn[m] = __ldg(As + m * 32);
            }
            uint32_t bb[4][2];
            #pragma unroll
            for (int n = 0; n < 4; n++) {
                const int px = wn * 32 + n * 8 + gid + dx;
                const uint32_t* p = stg + px * PXW + kk * 8 + tig;
                bb[n][0] = p[0];
                bb[n][1] = p[4];
            }
            #pragma unroll
            for (int m = 0; m < 4; m++) {
                const uint32_t* a = (const uint32_t*)&af[m];
                #pragma unroll
                for (int n = 0; n < 4; n++)
                    MMA_F16(acc[m][n], a, bb[n]);
            }
            if (kk < 7) {
                #pragma unroll
                for (int m = 0; m < 4; m++) af[m] = afn[m];
            }
        }
    };

    fill(0, stage[0]);
    __syncthreads();

    #pragma unroll 1
    for (int G = 0; G < 3; G++) {
        const int cur = G & 1;
        compute(stage[cur], G, 0);
        if (G < 2) fill(G + 1, stage[cur ^ 1]);   // LDG in flight across dx=1,2
        compute(stage[cur], G, 1);
        compute(stage[cur], G, 2);
        if (G < 2) __syncthreads();               // no barrier after last group
    }

    // ---- epilogue: demod + bias, float2 stores ----
    #pragma unroll
    for (int m = 0; m < 4; m++) {
        const int oc0 = (wm * 4 + m) * 16 + gid;
        const int oc1 = oc0 + 8;
        const float d0 = g_demod[b * COUT + oc0], bb0 = bias[oc0];
        const float d1 = g_demod[b * COUT + oc1], bb1 = bias[oc1];
        float* r0 = out + (((size_t)b * COUT + oc0) * HH + y) * WW;
        float* r1 = out + (((size_t)b * COUT + oc1) * HH + y) * WW;
        #pragma unroll
        for (int n = 0; n < 4; n++) {
            const int px = x0 + (wn * 4 + n) * 8 + tig * 2;
            float2 v0 = make_float2(acc[m][n][0] * d0 + bb0, acc[m][n][1] * d0 + bb0);
            float2 v1 = make_float2(acc[m][n][2] * d1 + bb1, acc[m][n][3] * d1 + bb1);
            *(float2*)(r0 + px) = v0;
            *(float2*)(r1 + px) = v1;
        }
    }
}

// ---------------------------------------------------------------------------
extern "C" void kernel_launch(void* const* d_in, const int* in_sizes, int n_in,
                              void* d_out, int out_size) {
    const float* x       = (const float*)d_in[0];
    const float* w       = (const float*)d_in[1];
    const float* weight  = (const float*)d_in[2];
    const float* style_W = (const float*)d_in[3];
    const float* style_b = (const float*)d_in[4];
    const float* bias    = (const float*)d_in[5];
    float* out = (float*)d_out;

    prep1<<<1344, 256>>>(w, style_W, style_b, weight);
    prep2<<<128, 256>>>();

    dim3 grid(2, HH, Bq);
    conv_mma_kernel<<<grid, 256>>>(x, bias, out);
}